// round 3
// baseline (speedup 1.0000x reference)
#include <cuda_runtime.h>
#include <math.h>

#define WDIM 512
#define LDIM 512
#define WL   (WDIM * LDIM)     // 262144 pixels
#define NTGT 64
#define TILE 16                 // 16x16 pixel tiles
#define TPB  (TILE * TILE)      // 256 threads
#define NBLK ((WDIM / TILE) * (LDIM / TILE))   // 1024 blocks

__device__ float        g_part[NBLK];
__device__ unsigned int g_done;   // zero-initialized; last block resets to 0

// logit(0.1) = ln(0.1/0.9)
#define LOGIT_THRESH (-2.1972245773362196f)

// ---------------------------------------------------------------------------
// Single fused kernel: decode + cull + IoU + loss; last finishing block
// reduces the per-block partials and writes the scalar output.
// ---------------------------------------------------------------------------
__global__ __launch_bounds__(TPB) void loss_kernel(
    const float* __restrict__ psm,    // [2, W, L]
    const float* __restrict__ rm,     // [14, W, L]
    const float* __restrict__ anc,    // [W, L, 2, 7]
    const float* __restrict__ Tm,     // [4, 4]
    const float* __restrict__ target, // [64, 7]
    float* __restrict__ out)
{
    const int tid = threadIdx.x;

    // ---- tile -> pixel mapping ----
    const int tile_i = blockIdx.x >> 5;          // /32
    const int tile_j = blockIdx.x & 31;
    const int i = tile_i * TILE + (tid >> 4);
    const int j = tile_j * TILE + (tid & 15);
    const int pix = i * LDIM + j;

    // ---- target standup boxes (threads 0..63, in registers) ----
    float tminx = 0.f, tminy = 0.f, tmaxx = 0.f, tmaxy = 0.f, tarea = 0.f;
    if (tid < NTGT) {
        const float* t = target + tid * 7;
        float X = t[0], Y = t[1];
        float w = t[4], l = t[5];
        float c, s;
        __sincosf(t[6], &s, &c);
        float ex = 0.5f * (fabsf(c) * l + fabsf(s) * w);
        float ey = 0.5f * (fabsf(s) * l + fabsf(c) * w);
        tminx = X - ex;  tmaxx = X + ex;
        tminy = Y - ey;  tmaxy = Y + ey;
        tarea = (2.0f * ex) * (2.0f * ey);
    }

    // ---- pred boxes for both anchors ----
    const float T00 = Tm[0], T01 = Tm[1], T02 = Tm[2], T03 = Tm[3];
    const float T10 = Tm[4], T11 = Tm[5], T12 = Tm[6], T13 = Tm[7];

    // anc per pixel: 14 contiguous floats at byte offset pix*56 (8B aligned)
    const float2* A2 = (const float2*)(anc + (size_t)pix * 14);
    float2 v0 = A2[0], v1 = A2[1], v2 = A2[2], v3 = A2[3],
           v4 = A2[4], v5 = A2[5], v6 = A2[6];
    const float av[14] = { v0.x, v0.y, v1.x, v1.y, v2.x, v2.y, v3.x,
                           v3.y, v4.x, v4.y, v5.x, v5.y, v6.x, v6.y };

    float px1[2], py1[2], px2[2], py2[2], area_t[2], wlog[2];

#pragma unroll
    for (int a = 0; a < 2; a++) {
        float xlogit = psm[a * WL + pix];
        // mask * log(1 - sigmoid(x)) = (x > logit(0.1)) ? -log(1+e^x) : 0
        wlog[a] = (xlogit > LOGIT_THRESH)
                    ? -__logf(1.0f + __expf(xlogit)) : 0.0f;

        float d0 = rm[(7 * a + 0) * WL + pix];
        float d1 = rm[(7 * a + 1) * WL + pix];
        float d2 = rm[(7 * a + 2) * WL + pix];
        float d3 = rm[(7 * a + 3) * WL + pix];
        float d4 = rm[(7 * a + 4) * WL + pix];
        float d5 = rm[(7 * a + 5) * WL + pix];
        float d6 = rm[(7 * a + 6) * WL + pix];

        float a0 = av[7 * a + 0], a1 = av[7 * a + 1], a2 = av[7 * a + 2];
        float a3 = av[7 * a + 3], a4 = av[7 * a + 4], a5 = av[7 * a + 5];
        float a6 = av[7 * a + 6];

        float dg = sqrtf(a4 * a4 + a5 * a5);
        float X = fmaf(d0, dg, a0);
        float Y = fmaf(d1, dg, a1);
        float Z = fmaf(d2, a3, a2);
        float hh = __expf(d3) * a3;
        float ww = __expf(d4) * a4;
        float ll = __expf(d5) * a5;

        float c, s;
        __sincosf(d6 + a6, &s, &c);

        float bx = fmaf(T00, X, fmaf(T01, Y, fmaf(T02, Z, T03)));
        float by = fmaf(T10, X, fmaf(T11, Y, fmaf(T12, Z, T13)));
        float ex = 0.5f * (fabsf(fmaf(T00, c,  T01 * s)) * ll +
                           fabsf(fmaf(T01, c, -T00 * s)) * ww +
                           fabsf(T02) * hh);
        float ey = 0.5f * (fabsf(fmaf(T10, c,  T11 * s)) * ll +
                           fabsf(fmaf(T11, c, -T10 * s)) * ww +
                           fabsf(T12) * hh);

        px1[a] = bx - ex;  px2[a] = bx + ex;
        py1[a] = by - ey;  py2[a] = by + ey;
        area_t[a] = (2.0f * ex) * (2.0f * ey);
    }

    // ---- block bounding box over all pred boxes ----
    float bminx = fminf(px1[0], px1[1]);
    float bminy = fminf(py1[0], py1[1]);
    float bmaxx = fmaxf(px2[0], px2[1]);
    float bmaxy = fmaxf(py2[0], py2[1]);

    __shared__ float s_minx[8], s_miny[8], s_maxx[8], s_maxy[8];
    __shared__ float s_bbox[4];
#pragma unroll
    for (int off = 16; off > 0; off >>= 1) {
        bminx = fminf(bminx, __shfl_xor_sync(0xFFFFFFFFu, bminx, off));
        bminy = fminf(bminy, __shfl_xor_sync(0xFFFFFFFFu, bminy, off));
        bmaxx = fmaxf(bmaxx, __shfl_xor_sync(0xFFFFFFFFu, bmaxx, off));
        bmaxy = fmaxf(bmaxy, __shfl_xor_sync(0xFFFFFFFFu, bmaxy, off));
    }
    const int lane = tid & 31;
    const int wid  = tid >> 5;
    if (lane == 0) {
        s_minx[wid] = bminx;  s_miny[wid] = bminy;
        s_maxx[wid] = bmaxx;  s_maxy[wid] = bmaxy;
    }
    __syncthreads();
    if (wid == 0) {
        float m0 = (lane < 8) ? s_minx[lane] :  1e30f;
        float m1 = (lane < 8) ? s_miny[lane] :  1e30f;
        float m2 = (lane < 8) ? s_maxx[lane] : -1e30f;
        float m3 = (lane < 8) ? s_maxy[lane] : -1e30f;
#pragma unroll
        for (int off = 4; off > 0; off >>= 1) {
            m0 = fminf(m0, __shfl_xor_sync(0xFFFFFFFFu, m0, off));
            m1 = fminf(m1, __shfl_xor_sync(0xFFFFFFFFu, m1, off));
            m2 = fmaxf(m2, __shfl_xor_sync(0xFFFFFFFFu, m2, off));
            m3 = fmaxf(m3, __shfl_xor_sync(0xFFFFFFFFu, m3, off));
        }
        if (lane == 0) {
            s_bbox[0] = m0;  s_bbox[1] = m1;  s_bbox[2] = m2;  s_bbox[3] = m3;
        }
    }
    __syncthreads();

    // ---- cull targets against block bbox, compact survivors to shared ----
    __shared__ int    s_cnt;
    __shared__ float4 s_cbox[NTGT];
    __shared__ float  s_carea[NTGT];
    if (tid == 0) s_cnt = 0;
    __syncthreads();
    if (tid < NTGT) {
        bool hit = (tminx <= s_bbox[2]) && (tmaxx >= s_bbox[0]) &&
                   (tminy <= s_bbox[3]) && (tmaxy >= s_bbox[1]);
        if (hit) {
            int idx = atomicAdd(&s_cnt, 1);
            s_cbox[idx]  = make_float4(tminx, tminy, tmaxx, tmaxy);
            s_carea[idx] = tarea;
        }
    }
    __syncthreads();
    const int cnt = s_cnt;

    // ---- IoU accumulation over surviving targets only ----
    float s0 = 0.0f, s1 = 0.0f;
    for (int m = 0; m < cnt; m++) {
        float4 tb = s_cbox[m];
        float ta = s_carea[m];
        {
            float wi = fminf(px2[0], tb.z) - fmaxf(px1[0], tb.x);
            float hi = fminf(py2[0], tb.w) - fmaxf(py1[0], tb.y);
            if (wi > 0.0f && hi > 0.0f) {
                float wh = wi * hi;
                s0 += __fdividef(wh, area_t[0] + ta - wh);
            }
        }
        {
            float wi = fminf(px2[1], tb.z) - fmaxf(px1[1], tb.x);
            float hi = fminf(py2[1], tb.w) - fmaxf(py1[1], tb.y);
            if (wi > 0.0f && hi > 0.0f) {
                float wh = wi * hi;
                s1 += __fdividef(wh, area_t[1] + ta - wh);
            }
        }
    }

    float local = wlog[0] * s0 + wlog[1] * s1;

    // ---- block sum -> g_part[blockIdx.x] ----
    __shared__ float red[8];
#pragma unroll
    for (int off = 16; off > 0; off >>= 1)
        local += __shfl_down_sync(0xFFFFFFFFu, local, off);
    if (lane == 0) red[wid] = local;
    __syncthreads();

    __shared__ bool s_islast;
    if (wid == 0) {
        float v = (lane < 8) ? red[lane] : 0.0f;
#pragma unroll
        for (int off = 4; off > 0; off >>= 1)
            v += __shfl_down_sync(0xFFFFFFFFu, v, off);
        if (lane == 0) {
            g_part[blockIdx.x] = v;
            __threadfence();                       // publish partial
            unsigned int t = atomicAdd(&g_done, 1u);
            s_islast = (t == NBLK - 1);
        }
    }
    __syncthreads();

    // ---- last block reduces all partials and writes output ----
    if (s_islast) {
        __threadfence();                           // acquire all partials
        float v = g_part[tid] + g_part[tid + 256] +
                  g_part[tid + 512] + g_part[tid + 768];
#pragma unroll
        for (int off = 16; off > 0; off >>= 1)
            v += __shfl_down_sync(0xFFFFFFFFu, v, off);
        if (lane == 0) red[wid] = v;
        __syncthreads();
        if (wid == 0) {
            float s = (lane < 8) ? red[lane] : 0.0f;
#pragma unroll
            for (int off = 4; off > 0; off >>= 1)
                s += __shfl_down_sync(0xFFFFFFFFu, s, off);
            if (lane == 0) {
                out[0] = s;
                g_done = 0;                        // reset for next graph replay
            }
        }
    }
}

extern "C" void kernel_launch(void* const* d_in, const int* in_sizes, int n_in,
                              void* d_out, int out_size) {
    const float* psm = (const float*)d_in[0];
    const float* rm  = (const float*)d_in[1];
    const float* anc = (const float*)d_in[2];
    const float* Tm  = (const float*)d_in[3];
    const float* tgt = (const float*)d_in[4];
    float* out = (float*)d_out;

    loss_kernel<<<NBLK, TPB>>>(psm, rm, anc, Tm, tgt, out);
}

// round 4
// speedup vs baseline: 1.2843x; 1.2843x over previous
#include <cuda_runtime.h>
#include <math.h>

#define WDIM 512
#define LDIM 512
#define WL   (WDIM * LDIM)      // 262144 pixels
#define NTGT 64
#define TPB  256
// tile = 16 rows x 32 cols; each thread handles 2 adjacent-j pixels
#define NBLK 512                // 32 i-tiles x 16 j-tiles

__device__ float g_part[NBLK];

// logit(0.1) = ln(0.1/0.9)
#define LOGIT_THRESH (-2.1972245773362196f)

// ---------------------------------------------------------------------------
// Main kernel: decode 2 pixels x 2 anchors per thread, block-level target
// culling, IoU over survivors, per-block partial sums.
// ---------------------------------------------------------------------------
__global__ __launch_bounds__(TPB, 3) void loss_kernel(
    const float* __restrict__ psm,    // [2, W, L]
    const float* __restrict__ rm,     // [14, W, L]
    const float* __restrict__ anc,    // [W, L, 2, 7]
    const float* __restrict__ Tm,     // [4, 4]
    const float* __restrict__ target) // [64, 7]
{
    const int tid = threadIdx.x;

    // ---- tile -> pixel-pair mapping ----
    const int tile_i = blockIdx.x >> 4;            // 0..31
    const int tile_j = blockIdx.x & 15;            // 0..15
    const int i  = tile_i * 16 + (tid >> 4);       // row
    const int jp = tile_j * 16 + (tid & 15);       // pixel-pair index
    const int pix0 = i * LDIM + jp * 2;            // even pixel

    // ---- front-batch all global loads (max MLP) ----
    const float4* A4 = (const float4*)(anc + (size_t)pix0 * 14);  // 28 floats
    float4 q[7];
#pragma unroll
    for (int k = 0; k < 7; k++) q[k] = A4[k];

    float2 rc[14];
#pragma unroll
    for (int c = 0; c < 14; c++)
        rc[c] = *(const float2*)(rm + (size_t)c * WL + pix0);

    const float2 sA = *(const float2*)(psm + pix0);        // anchor 0, pix0/pix1
    const float2 sB = *(const float2*)(psm + WL + pix0);   // anchor 1, pix0/pix1

    // ---- target standup boxes (threads 0..63; overlaps with loads in flight)
    float tminx = 0.f, tminy = 0.f, tmaxx = 0.f, tmaxy = 0.f, tarea = 0.f;
    if (tid < NTGT) {
        const float* t = target + tid * 7;
        float X = t[0], Y = t[1];
        float w = t[4], l = t[5];
        float c, s;
        __sincosf(t[6], &s, &c);
        float ex = 0.5f * (fabsf(c) * l + fabsf(s) * w);
        float ey = 0.5f * (fabsf(s) * l + fabsf(c) * w);
        tminx = X - ex;  tmaxx = X + ex;
        tminy = Y - ey;  tmaxy = Y + ey;
        tarea = (2.0f * ex) * (2.0f * ey);
    }

    const float T00 = Tm[0], T01 = Tm[1], T02 = Tm[2], T03 = Tm[3];
    const float T10 = Tm[4], T11 = Tm[5], T12 = Tm[6], T13 = Tm[7];

    // ---- decode 4 boxes: b = p*2 + a  (p = pixel-in-pair, a = anchor) ----
    float px1[4], py1[4], px2[4], py2[4], areat[4], wlog[4];

#pragma unroll
    for (int p = 0; p < 2; p++) {
#pragma unroll
        for (int a = 0; a < 2; a++) {
            const int b = p * 2 + a;

            float xl = (a == 0) ? (p == 0 ? sA.x : sA.y)
                                : (p == 0 ? sB.x : sB.y);
            wlog[b] = (xl > LOGIT_THRESH)
                        ? -__logf(1.0f + __expf(xl)) : 0.0f;

            // deltas: channel a*7+f, component p of the pair
            float d0 = (p == 0) ? rc[a * 7 + 0].x : rc[a * 7 + 0].y;
            float d1 = (p == 0) ? rc[a * 7 + 1].x : rc[a * 7 + 1].y;
            float d2 = (p == 0) ? rc[a * 7 + 2].x : rc[a * 7 + 2].y;
            float d3 = (p == 0) ? rc[a * 7 + 3].x : rc[a * 7 + 3].y;
            float d4 = (p == 0) ? rc[a * 7 + 4].x : rc[a * 7 + 4].y;
            float d5 = (p == 0) ? rc[a * 7 + 5].x : rc[a * 7 + 5].y;
            float d6 = (p == 0) ? rc[a * 7 + 6].x : rc[a * 7 + 6].y;

            // anchors: 28-float pack, field f of box b at index b*7+f
            float av[7];
#pragma unroll
            for (int f = 0; f < 7; f++) {
                const int idx = b * 7 + f;          // compile-time constant
                const float4 v = q[idx >> 2];
                av[f] = ((idx & 3) == 0) ? v.x :
                        ((idx & 3) == 1) ? v.y :
                        ((idx & 3) == 2) ? v.z : v.w;
            }

            float dg = sqrtf(av[4] * av[4] + av[5] * av[5]);
            float X = fmaf(d0, dg, av[0]);
            float Y = fmaf(d1, dg, av[1]);
            float Z = fmaf(d2, av[3], av[2]);
            float hh = __expf(d3) * av[3];
            float ww = __expf(d4) * av[4];
            float ll = __expf(d5) * av[5];

            float c, s;
            __sincosf(d6 + av[6], &s, &c);

            float bx = fmaf(T00, X, fmaf(T01, Y, fmaf(T02, Z, T03)));
            float by = fmaf(T10, X, fmaf(T11, Y, fmaf(T12, Z, T13)));
            float ex = 0.5f * (fabsf(fmaf(T00, c,  T01 * s)) * ll +
                               fabsf(fmaf(T01, c, -T00 * s)) * ww +
                               fabsf(T02) * hh);
            float ey = 0.5f * (fabsf(fmaf(T10, c,  T11 * s)) * ll +
                               fabsf(fmaf(T11, c, -T10 * s)) * ww +
                               fabsf(T12) * hh);

            px1[b] = bx - ex;  px2[b] = bx + ex;
            py1[b] = by - ey;  py2[b] = by + ey;
            areat[b] = (2.0f * ex) * (2.0f * ey);
        }
    }

    // ---- block bounding box over all 4 boxes per thread ----
    float bminx = fminf(fminf(px1[0], px1[1]), fminf(px1[2], px1[3]));
    float bminy = fminf(fminf(py1[0], py1[1]), fminf(py1[2], py1[3]));
    float bmaxx = fmaxf(fmaxf(px2[0], px2[1]), fmaxf(px2[2], px2[3]));
    float bmaxy = fmaxf(fmaxf(py2[0], py2[1]), fmaxf(py2[2], py2[3]));

    __shared__ float s_minx[8], s_miny[8], s_maxx[8], s_maxy[8];
    __shared__ float s_bbox[4];
#pragma unroll
    for (int off = 16; off > 0; off >>= 1) {
        bminx = fminf(bminx, __shfl_xor_sync(0xFFFFFFFFu, bminx, off));
        bminy = fminf(bminy, __shfl_xor_sync(0xFFFFFFFFu, bminy, off));
        bmaxx = fmaxf(bmaxx, __shfl_xor_sync(0xFFFFFFFFu, bmaxx, off));
        bmaxy = fmaxf(bmaxy, __shfl_xor_sync(0xFFFFFFFFu, bmaxy, off));
    }
    const int lane = tid & 31;
    const int wid  = tid >> 5;
    if (lane == 0) {
        s_minx[wid] = bminx;  s_miny[wid] = bminy;
        s_maxx[wid] = bmaxx;  s_maxy[wid] = bmaxy;
    }
    __syncthreads();
    if (wid == 0) {
        float m0 = (lane < 8) ? s_minx[lane] :  1e30f;
        float m1 = (lane < 8) ? s_miny[lane] :  1e30f;
        float m2 = (lane < 8) ? s_maxx[lane] : -1e30f;
        float m3 = (lane < 8) ? s_maxy[lane] : -1e30f;
#pragma unroll
        for (int off = 4; off > 0; off >>= 1) {
            m0 = fminf(m0, __shfl_xor_sync(0xFFFFFFFFu, m0, off));
            m1 = fminf(m1, __shfl_xor_sync(0xFFFFFFFFu, m1, off));
            m2 = fmaxf(m2, __shfl_xor_sync(0xFFFFFFFFu, m2, off));
            m3 = fmaxf(m3, __shfl_xor_sync(0xFFFFFFFFu, m3, off));
        }
        if (lane == 0) {
            s_bbox[0] = m0;  s_bbox[1] = m1;  s_bbox[2] = m2;  s_bbox[3] = m3;
        }
    }
    __syncthreads();

    // ---- cull targets against block bbox ----
    __shared__ int    s_cnt;
    __shared__ float4 s_cbox[NTGT];
    __shared__ float  s_carea[NTGT];
    if (tid == 0) s_cnt = 0;
    __syncthreads();
    if (tid < NTGT) {
        bool hit = (tminx <= s_bbox[2]) && (tmaxx >= s_bbox[0]) &&
                   (tminy <= s_bbox[3]) && (tmaxy >= s_bbox[1]);
        if (hit) {
            int idx = atomicAdd(&s_cnt, 1);
            s_cbox[idx]  = make_float4(tminx, tminy, tmaxx, tmaxy);
            s_carea[idx] = tarea;
        }
    }
    __syncthreads();
    const int cnt = s_cnt;

    // ---- IoU over survivors for all 4 boxes ----
    float acc[4] = {0.f, 0.f, 0.f, 0.f};
    for (int m = 0; m < cnt; m++) {
        const float4 tb = s_cbox[m];
        const float  ta = s_carea[m];
#pragma unroll
        for (int b = 0; b < 4; b++) {
            float wi = fminf(px2[b], tb.z) - fmaxf(px1[b], tb.x);
            float hi = fminf(py2[b], tb.w) - fmaxf(py1[b], tb.y);
            if (wi > 0.0f && hi > 0.0f) {
                float wh = wi * hi;
                acc[b] += __fdividef(wh, areat[b] + ta - wh);
            }
        }
    }

    float local = wlog[0] * acc[0] + wlog[1] * acc[1] +
                  wlog[2] * acc[2] + wlog[3] * acc[3];

    // ---- block sum -> g_part ----
    __shared__ float red[8];
#pragma unroll
    for (int off = 16; off > 0; off >>= 1)
        local += __shfl_down_sync(0xFFFFFFFFu, local, off);
    if (lane == 0) red[wid] = local;
    __syncthreads();
    if (wid == 0) {
        float v = (lane < 8) ? red[lane] : 0.0f;
#pragma unroll
        for (int off = 4; off > 0; off >>= 1)
            v += __shfl_down_sync(0xFFFFFFFFu, v, off);
        if (lane == 0) g_part[blockIdx.x] = v;
    }
}

// ---------------------------------------------------------------------------
// Finalize: reduce 512 per-block partials to the scalar output.
// ---------------------------------------------------------------------------
__global__ __launch_bounds__(NBLK) void finalize_kernel(float* __restrict__ out) {
    int tid = threadIdx.x;
    float v = g_part[tid];
    __shared__ float red[16];
#pragma unroll
    for (int off = 16; off > 0; off >>= 1)
        v += __shfl_down_sync(0xFFFFFFFFu, v, off);
    int lane = tid & 31, wid = tid >> 5;
    if (lane == 0) red[wid] = v;
    __syncthreads();
    if (wid == 0) {
        float s = (lane < 16) ? red[lane] : 0.0f;
#pragma unroll
        for (int off = 8; off > 0; off >>= 1)
            s += __shfl_down_sync(0xFFFFFFFFu, s, off);
        if (lane == 0) out[0] = s;
    }
}

extern "C" void kernel_launch(void* const* d_in, const int* in_sizes, int n_in,
                              void* d_out, int out_size) {
    const float* psm = (const float*)d_in[0];
    const float* rm  = (const float*)d_in[1];
    const float* anc = (const float*)d_in[2];
    const float* Tm  = (const float*)d_in[3];
    const float* tgt = (const float*)d_in[4];
    float* out = (float*)d_out;

    loss_kernel<<<NBLK, TPB>>>(psm, rm, anc, Tm, tgt);
    finalize_kernel<<<1, NBLK>>>(out);
}